// round 1
// baseline (speedup 1.0000x reference)
#include <cuda_runtime.h>
#include <math.h>

#define BN 16384
#define DN 256
#define PN 512
#define CN 20

// Scratch (device globals: no allocations allowed)
__device__ float g_s[PN * BN];      // s[k][b], 32 MB — fits in L2
__device__ float g_U[PN * CN];      // U[k][c]
__device__ float g_A[PN];           // alphap[k]*exp(-g2[k]*0.5*||W_k||^2)
__device__ float g_g2[PN];          // gamma[k]^2
__device__ float g_hx[BN];          // 0.5*||x_b||^2

// ---------------------------------------------------------------------------
// Prep per-prototype quantities: one warp per k
// ---------------------------------------------------------------------------
__global__ void prep_proto_kernel(const float* __restrict__ W,
                                  const float* __restrict__ BETA,
                                  const float* __restrict__ alpha,
                                  const float* __restrict__ gamma) {
    int k = blockIdx.x;
    int lane = threadIdx.x;

    // ||W_k||^2
    float sum = 0.f;
    const float4* wr = (const float4*)(W + k * DN);
#pragma unroll
    for (int i = 0; i < DN / 4 / 32; i++) {  // 2 iters
        float4 v = wr[lane + i * 32];
        sum += v.x * v.x + v.y * v.y + v.z * v.z + v.w * v.w;
    }
#pragma unroll
    for (int o = 16; o; o >>= 1) sum += __shfl_xor_sync(0xffffffffu, sum, o);

    // U row: beta^2 / rowsum(beta^2)
    float b2 = 0.f;
    if (lane < CN) {
        float bb = BETA[k * CN + lane];
        b2 = bb * bb;
    }
    float bsum = b2;
#pragma unroll
    for (int o = 16; o; o >>= 1) bsum += __shfl_xor_sync(0xffffffffu, bsum, o);
    if (lane < CN) g_U[k * CN + lane] = b2 / bsum;

    if (lane == 0) {
        float g  = gamma[k];
        float g2 = g * g;
        float ap = 0.99f / (1.f + expf(-alpha[k]));
        g_g2[k] = g2;
        g_A[k]  = ap * expf(-g2 * 0.5f * sum);
    }
}

// ---------------------------------------------------------------------------
// Prep per-batch 0.5*||x||^2: one warp per row
// ---------------------------------------------------------------------------
__global__ void prep_x_kernel(const float* __restrict__ X) {
    int gwarp = (blockIdx.x * blockDim.x + threadIdx.x) >> 5;
    int lane  = threadIdx.x & 31;
    float sum = 0.f;
    const float4* xr = (const float4*)(X + gwarp * DN);
#pragma unroll
    for (int i = 0; i < DN / 4 / 32; i++) {  // 2 iters
        float4 v = xr[lane + i * 32];
        sum += v.x * v.x + v.y * v.y + v.z * v.z + v.w * v.w;
    }
#pragma unroll
    for (int o = 16; o; o >>= 1) sum += __shfl_xor_sync(0xffffffffu, sum, o);
    if (lane == 0) g_hx[gwarp] = 0.5f * sum;
}

// ---------------------------------------------------------------------------
// GEMM + s epilogue. Tile: 128 batch x 64 proto, 256 threads, 8x4 per thread.
// Smem stored d-major (transposed) with padded rows for LDS.128 inner loop.
// s[k][b] = A[k] * exp(g2[k]*(dot - hx[b]))
// ---------------------------------------------------------------------------
__global__ void __launch_bounds__(256) gemm_s_kernel(const float* __restrict__ X,
                                                     const float* __restrict__ W) {
    __shared__ float Xs[32][132];  // [dd][b], pad 4 -> 16B-aligned rows, conflict-free STS
    __shared__ float Ws[32][68];   // [dd][p]

    const int b0 = blockIdx.x * 128;
    const int p0 = blockIdx.y * 64;
    const int t  = threadIdx.x;
    const int tb = t & 15;   // 16 groups of 8 batch
    const int tp = t >> 4;   // 16 groups of 4 protos

    float acc[8][4];
#pragma unroll
    for (int i = 0; i < 8; i++)
#pragma unroll
        for (int j = 0; j < 4; j++) acc[i][j] = 0.f;

    for (int d0 = 0; d0 < DN; d0 += 32) {
        // X tile: 128 rows x 32 d = 1024 float4 loads / 256 threads = 4 each
#pragma unroll
        for (int i = 0; i < 4; i++) {
            int idx = t + i * 256;
            int row = idx >> 3;
            int c4  = (idx & 7) * 4;
            float4 v = *(const float4*)(X + (b0 + row) * DN + d0 + c4);
            Xs[c4 + 0][row] = v.x;
            Xs[c4 + 1][row] = v.y;
            Xs[c4 + 2][row] = v.z;
            Xs[c4 + 3][row] = v.w;
        }
        // W tile: 64 rows x 32 d = 512 float4 loads / 256 threads = 2 each
#pragma unroll
        for (int i = 0; i < 2; i++) {
            int idx = t + i * 256;
            int row = idx >> 3;
            int c4  = (idx & 7) * 4;
            float4 v = *(const float4*)(W + (p0 + row) * DN + d0 + c4);
            Ws[c4 + 0][row] = v.x;
            Ws[c4 + 1][row] = v.y;
            Ws[c4 + 2][row] = v.z;
            Ws[c4 + 3][row] = v.w;
        }
        __syncthreads();

#pragma unroll
        for (int dd = 0; dd < 32; dd++) {
            float4 xa = *(const float4*)(&Xs[dd][tb * 8]);
            float4 xb = *(const float4*)(&Xs[dd][tb * 8 + 4]);
            float4 wv = *(const float4*)(&Ws[dd][tp * 4]);
            float xr[8] = {xa.x, xa.y, xa.z, xa.w, xb.x, xb.y, xb.z, xb.w};
            float wr[4] = {wv.x, wv.y, wv.z, wv.w};
#pragma unroll
            for (int i = 0; i < 8; i++)
#pragma unroll
                for (int j = 0; j < 4; j++)
                    acc[i][j] += xr[i] * wr[j];
        }
        __syncthreads();
    }

    // Epilogue: s = A * exp(g2*(dot - hx))
    float hx[8];
#pragma unroll
    for (int i = 0; i < 8; i++) hx[i] = g_hx[b0 + tb * 8 + i];

#pragma unroll
    for (int j = 0; j < 4; j++) {
        int p    = p0 + tp * 4 + j;
        float g2 = g_g2[p];
        float A  = g_A[p];
#pragma unroll
        for (int i = 0; i < 8; i++) {
            g_s[p * BN + b0 + tb * 8 + i] = A * expf(g2 * (acc[i][j] - hx[i]));
        }
    }
}

// ---------------------------------------------------------------------------
// Scan: one thread per batch element, 21-element state in registers.
// Double-buffered 8-wide prefetch of s (L2-resident).
// ---------------------------------------------------------------------------
__global__ void __launch_bounds__(256) scan_kernel(float* __restrict__ out) {
    __shared__ float Us[PN * CN];  // 40 KB
    for (int i = threadIdx.x; i < PN * CN; i += 256) Us[i] = g_U[i];
    __syncthreads();

    const int b = blockIdx.x * 256 + threadIdx.x;

    float mc[CN];
#pragma unroll
    for (int c = 0; c < CN; c++) mc[c] = 0.f;
    float mn = 1.f;

    float cur[8], nxt[8];
#pragma unroll
    for (int i = 0; i < 8; i++) cur[i] = g_s[i * BN + b];

    for (int kc = 0; kc < PN; kc += 8) {
        if (kc + 8 < PN) {
#pragma unroll
            for (int i = 0; i < 8; i++) nxt[i] = g_s[(kc + 8 + i) * BN + b];
        }
#pragma unroll
        for (int i = 0; i < 8; i++) {
            float sk  = cur[i];
            float mn1 = 1.f - sk;
            const float* u = &Us[(kc + i) * CN];
#pragma unroll
            for (int c = 0; c < CN; c++) {
                float m = u[c] * sk;
                mc[c] = mc[c] * (m + mn1) + m * mn;
            }
            mn *= mn1;
        }
#pragma unroll
        for (int i = 0; i < 8; i++) cur[i] = nxt[i];
    }

    float K = mn;
#pragma unroll
    for (int c = 0; c < CN; c++) K += mc[c];
    float r = 1.f / K;

#pragma unroll
    for (int c = 0; c < CN; c++) out[b * (CN + 1) + c] = mc[c] * r;
    out[b * (CN + 1) + CN] = mn * r;
}

// ---------------------------------------------------------------------------
extern "C" void kernel_launch(void* const* d_in, const int* in_sizes, int n_in,
                              void* d_out, int out_size) {
    const float* X     = (const float*)d_in[0];  // (B, D)
    const float* W     = (const float*)d_in[1];  // (P, D)
    const float* BETA  = (const float*)d_in[2];  // (P, C)
    const float* alpha = (const float*)d_in[3];  // (P, 1)
    const float* gamma = (const float*)d_in[4];  // (P, 1)
    float* out = (float*)d_out;                  // (B, C+1)

    prep_proto_kernel<<<PN, 32>>>(W, BETA, alpha, gamma);
    prep_x_kernel<<<BN / 8, 256>>>(X);

    dim3 grid(BN / 128, PN / 64);
    gemm_s_kernel<<<grid, 256>>>(X, W);

    scan_kernel<<<BN / 256, 256>>>(out);
}

// round 2
// speedup vs baseline: 1.5088x; 1.5088x over previous
#include <cuda_runtime.h>
#include <math.h>

#define BN 16384
#define DN 256
#define PN 512
#define CN 20
#define NSEG 8
#define SEGL (PN / NSEG)   // 64

// Scratch (device globals: no allocations allowed)
__device__ float g_s[PN * BN];           // s[k][b], 32 MB — L2-resident
__device__ float g_U[PN * CN];           // U[k][c]
__device__ float g_A[PN];                // alphap[k]*exp(-g2[k]*0.5*||W_k||^2)
__device__ float g_g2[PN];               // gamma[k]^2
__device__ float g_hx[BN];               // 0.5*||x_b||^2
__device__ float g_segA[NSEG][CN][BN];   // segment transform A (per class)
__device__ float g_segB[NSEG][CN][BN];   // segment transform B (per class)
__device__ float g_segD[NSEG][BN];       // segment transform D

// ---------------------------------------------------------------------------
// Prep per-prototype quantities: one warp per k
// ---------------------------------------------------------------------------
__global__ void prep_proto_kernel(const float* __restrict__ W,
                                  const float* __restrict__ BETA,
                                  const float* __restrict__ alpha,
                                  const float* __restrict__ gamma) {
    int k = blockIdx.x;
    int lane = threadIdx.x;

    float sum = 0.f;
    const float4* wr = (const float4*)(W + k * DN);
#pragma unroll
    for (int i = 0; i < DN / 4 / 32; i++) {
        float4 v = wr[lane + i * 32];
        sum += v.x * v.x + v.y * v.y + v.z * v.z + v.w * v.w;
    }
#pragma unroll
    for (int o = 16; o; o >>= 1) sum += __shfl_xor_sync(0xffffffffu, sum, o);

    float b2 = 0.f;
    if (lane < CN) {
        float bb = BETA[k * CN + lane];
        b2 = bb * bb;
    }
    float bsum = b2;
#pragma unroll
    for (int o = 16; o; o >>= 1) bsum += __shfl_xor_sync(0xffffffffu, bsum, o);
    if (lane < CN) g_U[k * CN + lane] = b2 / bsum;

    if (lane == 0) {
        float g  = gamma[k];
        float g2 = g * g;
        float ap = 0.99f / (1.f + expf(-alpha[k]));
        g_g2[k] = g2;
        g_A[k]  = ap * expf(-g2 * 0.5f * sum);
    }
}

// ---------------------------------------------------------------------------
// Prep per-batch 0.5*||x||^2: one warp per row
// ---------------------------------------------------------------------------
__global__ void prep_x_kernel(const float* __restrict__ X) {
    int gwarp = (blockIdx.x * blockDim.x + threadIdx.x) >> 5;
    int lane  = threadIdx.x & 31;
    float sum = 0.f;
    const float4* xr = (const float4*)(X + gwarp * DN);
#pragma unroll
    for (int i = 0; i < DN / 4 / 32; i++) {
        float4 v = xr[lane + i * 32];
        sum += v.x * v.x + v.y * v.y + v.z * v.z + v.w * v.w;
    }
#pragma unroll
    for (int o = 16; o; o >>= 1) sum += __shfl_xor_sync(0xffffffffu, sum, o);
    if (lane == 0) g_hx[gwarp] = 0.5f * sum;
}

// ---------------------------------------------------------------------------
// GEMM + s epilogue. Tile 128 b x 128 p, 256 threads, 8x8 per thread
// (split as 2x float4 chunks per dim for LDS.128 reads and float4 stores).
// s[k][b] = A[k] * exp(g2[k]*(dot - hx[b]))
// ---------------------------------------------------------------------------
__global__ void __launch_bounds__(256, 2) gemm_s_kernel(const float* __restrict__ X,
                                                        const float* __restrict__ W) {
    __shared__ float Xs[32][132];  // [dd][b]
    __shared__ float Ws[32][132];  // [dd][p]

    const int b0 = blockIdx.x * 128;
    const int p0 = blockIdx.y * 128;
    const int t  = threadIdx.x;
    const int tb = t & 15;   // 16 groups; b chunks at tb*4 and 64+tb*4
    const int tp = t >> 4;   // 16 groups; p chunks at tp*4 and 64+tp*4

    float acc[8][8];
#pragma unroll
    for (int i = 0; i < 8; i++)
#pragma unroll
        for (int j = 0; j < 8; j++) acc[i][j] = 0.f;

    for (int d0 = 0; d0 < DN; d0 += 32) {
        // load both 128x32 tiles: 1024 float4 each / 256 threads = 4 each
#pragma unroll
        for (int i = 0; i < 4; i++) {
            int idx = t + i * 256;
            int row = idx >> 3;
            int c4  = (idx & 7) * 4;
            float4 v = *(const float4*)(X + (b0 + row) * DN + d0 + c4);
            Xs[c4 + 0][row] = v.x;
            Xs[c4 + 1][row] = v.y;
            Xs[c4 + 2][row] = v.z;
            Xs[c4 + 3][row] = v.w;
            float4 w = *(const float4*)(W + (p0 + row) * DN + d0 + c4);
            Ws[c4 + 0][row] = w.x;
            Ws[c4 + 1][row] = w.y;
            Ws[c4 + 2][row] = w.z;
            Ws[c4 + 3][row] = w.w;
        }
        __syncthreads();

#pragma unroll
        for (int dd = 0; dd < 32; dd++) {
            float4 x0 = *(const float4*)(&Xs[dd][tb * 4]);
            float4 x1 = *(const float4*)(&Xs[dd][64 + tb * 4]);
            float4 w0 = *(const float4*)(&Ws[dd][tp * 4]);
            float4 w1 = *(const float4*)(&Ws[dd][64 + tp * 4]);
            float xr[8] = {x0.x, x0.y, x0.z, x0.w, x1.x, x1.y, x1.z, x1.w};
            float wr[8] = {w0.x, w0.y, w0.z, w0.w, w1.x, w1.y, w1.z, w1.w};
#pragma unroll
            for (int i = 0; i < 8; i++)
#pragma unroll
                for (int j = 0; j < 8; j++)
                    acc[i][j] += xr[i] * wr[j];
        }
        __syncthreads();
    }

    // Epilogue
    float hx[8];
#pragma unroll
    for (int i = 0; i < 8; i++) {
        int b = b0 + ((i < 4) ? (tb * 4 + i) : (64 + tb * 4 + i - 4));
        hx[i] = g_hx[b];
    }

#pragma unroll
    for (int j = 0; j < 8; j++) {
        int p    = p0 + ((j < 4) ? (tp * 4 + j) : (64 + tp * 4 + j - 4));
        float g2 = g_g2[p];
        float A  = g_A[p];
        float4 lo, hi;
        lo.x = A * expf(g2 * (acc[0][j] - hx[0]));
        lo.y = A * expf(g2 * (acc[1][j] - hx[1]));
        lo.z = A * expf(g2 * (acc[2][j] - hx[2]));
        lo.w = A * expf(g2 * (acc[3][j] - hx[3]));
        hi.x = A * expf(g2 * (acc[4][j] - hx[4]));
        hi.y = A * expf(g2 * (acc[5][j] - hx[5]));
        hi.z = A * expf(g2 * (acc[6][j] - hx[6]));
        hi.w = A * expf(g2 * (acc[7][j] - hx[7]));
        *(float4*)(&g_s[p * BN + b0 + tb * 4])      = lo;
        *(float4*)(&g_s[p * BN + b0 + 64 + tb * 4]) = hi;
    }
}

// ---------------------------------------------------------------------------
// Scan segments: affine transform composition. Each thread owns one
// (b, segment): computes A[20], B[20], D over SEGL=64 prototype steps.
//   a = U*s + (1-s);  B' = a*(B+D) - (1-s)*D;  A' = a*A;  D' = (1-s)*D
// ---------------------------------------------------------------------------
__global__ void __launch_bounds__(256) scan_seg_kernel() {
    __shared__ float Us[SEGL][CN];  // 5 KB
    const int seg = blockIdx.y;
    const int k0  = seg * SEGL;
    for (int i = threadIdx.x; i < SEGL * CN; i += 256)
        ((float*)Us)[i] = g_U[k0 * CN + i];
    __syncthreads();

    const int b = blockIdx.x * 256 + threadIdx.x;

    float A[CN], B[CN], D = 1.f;
#pragma unroll
    for (int c = 0; c < CN; c++) { A[c] = 1.f; B[c] = 0.f; }

    float cur[8], nxt[8];
#pragma unroll
    for (int i = 0; i < 8; i++) cur[i] = g_s[(k0 + i) * BN + b];

    for (int kk = 0; kk < SEGL; kk += 8) {
        if (kk + 8 < SEGL) {
#pragma unroll
            for (int i = 0; i < 8; i++) nxt[i] = g_s[(k0 + kk + 8 + i) * BN + b];
        }
#pragma unroll
        for (int i = 0; i < 8; i++) {
            float sk  = cur[i];
            float mn1 = 1.f - sk;
            float h   = mn1 * D;
            const float4* u4 = (const float4*)(&Us[kk + i][0]);
#pragma unroll
            for (int c4 = 0; c4 < 5; c4++) {
                float4 u = u4[c4];
                int c = c4 * 4;
                float a0 = fmaf(u.x, sk, mn1);
                float a1 = fmaf(u.y, sk, mn1);
                float a2 = fmaf(u.z, sk, mn1);
                float a3 = fmaf(u.w, sk, mn1);
                B[c + 0] = fmaf(a0, B[c + 0] + D, -h);
                B[c + 1] = fmaf(a1, B[c + 1] + D, -h);
                B[c + 2] = fmaf(a2, B[c + 2] + D, -h);
                B[c + 3] = fmaf(a3, B[c + 3] + D, -h);
                A[c + 0] *= a0;
                A[c + 1] *= a1;
                A[c + 2] *= a2;
                A[c + 3] *= a3;
            }
            D *= mn1;
        }
#pragma unroll
        for (int i = 0; i < 8; i++) cur[i] = nxt[i];
    }

#pragma unroll
    for (int c = 0; c < CN; c++) {
        g_segA[seg][c][b] = A[c];
        g_segB[seg][c][b] = B[c];
    }
    g_segD[seg][b] = D;
}

// ---------------------------------------------------------------------------
// Combine segments + normalize. 4 threads per b, 5 classes each; K reduced
// via shfl over the 4-lane group.
// ---------------------------------------------------------------------------
__global__ void __launch_bounds__(256) combine_kernel(float* __restrict__ out) {
    const int gt = blockIdx.x * 256 + threadIdx.x;
    const int b  = gt >> 2;
    const int cg = gt & 3;          // classes cg*5 .. cg*5+4

    float Bres[5], Dres;
    float Dseg[NSEG];
#pragma unroll
    for (int s = 0; s < NSEG; s++) Dseg[s] = g_segD[s][b];

#pragma unroll
    for (int j = 0; j < 5; j++) Bres[j] = g_segB[0][cg * 5 + j][b];
    Dres = Dseg[0];

#pragma unroll
    for (int s = 1; s < NSEG; s++) {
#pragma unroll
        for (int j = 0; j < 5; j++) {
            int c = cg * 5 + j;
            Bres[j] = Bres[j] * g_segA[s][c][b] + Dres * g_segB[s][c][b];
        }
        Dres *= Dseg[s];
    }

    float K = 0.f;
#pragma unroll
    for (int j = 0; j < 5; j++) K += Bres[j];
    K += __shfl_xor_sync(0xffffffffu, K, 1);
    K += __shfl_xor_sync(0xffffffffu, K, 2);
    K += Dres;  // Dres identical across the 4 lanes of this b
    float r = 1.f / K;

#pragma unroll
    for (int j = 0; j < 5; j++) out[b * (CN + 1) + cg * 5 + j] = Bres[j] * r;
    if (cg == 3) out[b * (CN + 1) + CN] = Dres * r;
}

// ---------------------------------------------------------------------------
extern "C" void kernel_launch(void* const* d_in, const int* in_sizes, int n_in,
                              void* d_out, int out_size) {
    const float* X     = (const float*)d_in[0];  // (B, D)
    const float* W     = (const float*)d_in[1];  // (P, D)
    const float* BETA  = (const float*)d_in[2];  // (P, C)
    const float* alpha = (const float*)d_in[3];  // (P, 1)
    const float* gamma = (const float*)d_in[4];  // (P, 1)
    float* out = (float*)d_out;                  // (B, C+1)

    prep_proto_kernel<<<PN, 32>>>(W, BETA, alpha, gamma);
    prep_x_kernel<<<BN / 8, 256>>>(X);

    dim3 grid(BN / 128, PN / 128);
    gemm_s_kernel<<<grid, 256>>>(X, W);

    dim3 sgrid(BN / 256, NSEG);
    scan_seg_kernel<<<sgrid, 256>>>();

    combine_kernel<<<BN * 4 / 256, 256>>>(out);
}

// round 6
// speedup vs baseline: 2.0946x; 1.3882x over previous
#include <cuda_runtime.h>
#include <cuda_bf16.h>
#include <stdint.h>
#include <math.h>

#define BN 16384
#define DN 256
#define PN 512
#define CN 20
#define NSEG 8
#define SEGL (PN / NSEG)   // 64

// ---------------------------------------------------------------------------
// Device-global scratch (no allocations allowed)
// ---------------------------------------------------------------------------
__device__ float g_s[(size_t)PN * BN];   // s[k][b], 32 MB
__device__ float g_U[PN * CN];
__device__ float g_A[PN];                // alphap*exp(-g2*0.5*||W||^2)
__device__ float g_g2l[PN];              // g2 * log2(e)
__device__ float g_hx[BN];               // 0.5*||x_b||^2
__device__ float g_segA[NSEG][CN][BN];
__device__ float g_segB[NSEG][CN][BN];
__device__ float g_segD[NSEG][BN];

__device__ __nv_bfloat16 g_Xh[(size_t)BN * DN];
__device__ __nv_bfloat16 g_Xl[(size_t)BN * DN];
__device__ __nv_bfloat16 g_Wh[PN * DN];
__device__ __nv_bfloat16 g_Wl[PN * DN];

#define SW128(off) ((off) ^ (((off) >> 3) & 0x70))

// ---------------------------------------------------------------------------
// mma.sync / ldmatrix wrappers (base sm_103 features, NOT tcgen05)
// ---------------------------------------------------------------------------
__device__ __forceinline__ void ldsm_x4(uint32_t& r0, uint32_t& r1, uint32_t& r2,
                                        uint32_t& r3, uint32_t addr) {
    asm volatile("ldmatrix.sync.aligned.m8n8.x4.shared.b16 {%0,%1,%2,%3}, [%4];"
                 : "=r"(r0), "=r"(r1), "=r"(r2), "=r"(r3) : "r"(addr));
}
__device__ __forceinline__ void mma16816(float* d, const uint32_t* a, const uint32_t* b) {
    asm volatile("mma.sync.aligned.m16n8k16.row.col.f32.bf16.bf16.f32 "
                 "{%0,%1,%2,%3}, {%4,%5,%6,%7}, {%8,%9}, {%0,%1,%2,%3};"
                 : "+f"(d[0]), "+f"(d[1]), "+f"(d[2]), "+f"(d[3])
                 : "r"(a[0]), "r"(a[1]), "r"(a[2]), "r"(a[3]), "r"(b[0]), "r"(b[1]));
}
__device__ __forceinline__ uint32_t smem_u32(const void* p) {
    uint32_t a;
    asm("{ .reg .u64 t; cvta.to.shared.u64 t, %1; cvt.u32.u64 %0, t; }" : "=r"(a) : "l"(p));
    return a;
}

// ---------------------------------------------------------------------------
// Prep per-prototype: ||W||^2, U row, A, g2*log2e, and W -> bf16 hi/lo
// ---------------------------------------------------------------------------
__global__ void prep_proto_kernel(const float* __restrict__ W,
                                  const float* __restrict__ BETA,
                                  const float* __restrict__ alpha,
                                  const float* __restrict__ gamma) {
    int k = blockIdx.x;
    int lane = threadIdx.x;

    float sum = 0.f;
    const float4* wr = (const float4*)(W + k * DN);
#pragma unroll
    for (int i = 0; i < 2; i++) {
        float4 v = wr[lane + i * 32];
        sum += v.x * v.x + v.y * v.y + v.z * v.z + v.w * v.w;
        int base = k * DN + (lane + i * 32) * 4;
        __nv_bfloat16 h0 = __float2bfloat16(v.x);
        __nv_bfloat16 h1 = __float2bfloat16(v.y);
        __nv_bfloat16 h2 = __float2bfloat16(v.z);
        __nv_bfloat16 h3 = __float2bfloat16(v.w);
        __nv_bfloat16 l0 = __float2bfloat16(v.x - __bfloat162float(h0));
        __nv_bfloat16 l1 = __float2bfloat16(v.y - __bfloat162float(h1));
        __nv_bfloat16 l2 = __float2bfloat16(v.z - __bfloat162float(h2));
        __nv_bfloat16 l3 = __float2bfloat16(v.w - __bfloat162float(h3));
        *(__nv_bfloat162*)(g_Wh + base)     = __nv_bfloat162(h0, h1);
        *(__nv_bfloat162*)(g_Wh + base + 2) = __nv_bfloat162(h2, h3);
        *(__nv_bfloat162*)(g_Wl + base)     = __nv_bfloat162(l0, l1);
        *(__nv_bfloat162*)(g_Wl + base + 2) = __nv_bfloat162(l2, l3);
    }
#pragma unroll
    for (int o = 16; o; o >>= 1) sum += __shfl_xor_sync(0xffffffffu, sum, o);

    float b2 = 0.f;
    if (lane < CN) {
        float bb = BETA[k * CN + lane];
        b2 = bb * bb;
    }
    float bsum = b2;
#pragma unroll
    for (int o = 16; o; o >>= 1) bsum += __shfl_xor_sync(0xffffffffu, bsum, o);
    if (lane < CN) g_U[k * CN + lane] = b2 / bsum;

    if (lane == 0) {
        float g  = gamma[k];
        float g2 = g * g;
        float ap = 0.99f / (1.f + expf(-alpha[k]));
        g_g2l[k] = g2 * 1.4426950408889634f;
        g_A[k]   = ap * expf(-g2 * 0.5f * sum);
    }
}

// ---------------------------------------------------------------------------
// Prep per-batch: 0.5*||x||^2 and X -> bf16 hi/lo. One warp per row.
// ---------------------------------------------------------------------------
__global__ void prep_x_kernel(const float* __restrict__ X) {
    int row  = blockIdx.x * 8 + (threadIdx.x >> 5);
    int lane = threadIdx.x & 31;
    float sum = 0.f;
    const float4* xr = (const float4*)(X + (size_t)row * DN);
#pragma unroll
    for (int i = 0; i < 2; i++) {
        float4 v = xr[lane + i * 32];
        sum += v.x * v.x + v.y * v.y + v.z * v.z + v.w * v.w;
        size_t base = (size_t)row * DN + (lane + i * 32) * 4;
        __nv_bfloat16 h0 = __float2bfloat16(v.x);
        __nv_bfloat16 h1 = __float2bfloat16(v.y);
        __nv_bfloat16 h2 = __float2bfloat16(v.z);
        __nv_bfloat16 h3 = __float2bfloat16(v.w);
        __nv_bfloat16 l0 = __float2bfloat16(v.x - __bfloat162float(h0));
        __nv_bfloat16 l1 = __float2bfloat16(v.y - __bfloat162float(h1));
        __nv_bfloat16 l2 = __float2bfloat16(v.z - __bfloat162float(h2));
        __nv_bfloat16 l3 = __float2bfloat16(v.w - __bfloat162float(h3));
        *(__nv_bfloat162*)(g_Xh + base)     = __nv_bfloat162(h0, h1);
        *(__nv_bfloat162*)(g_Xh + base + 2) = __nv_bfloat162(h2, h3);
        *(__nv_bfloat162*)(g_Xl + base)     = __nv_bfloat162(l0, l1);
        *(__nv_bfloat162*)(g_Xl + base + 2) = __nv_bfloat162(l2, l3);
    }
#pragma unroll
    for (int o = 16; o; o >>= 1) sum += __shfl_xor_sync(0xffffffffu, sum, o);
    if (lane == 0) g_hx[row] = 0.5f * sum;
}

// ---------------------------------------------------------------------------
// HMMA GEMM: D[b,p] = sum over K=768 of [Xh|Xl|Xh].[Wh|Wh|Wl]
// Block 128b x 256p, 512 threads; warp tile 64x32 (2x8 warp grid).
// 12 chunks of K=64, double-buffered. Epilogue: exp2 poly -> smem transpose
// stage -> coalesced g_s[p][b] writes (two p-halves).
// ---------------------------------------------------------------------------
#define SM_A0 0
#define SM_A1 16384
#define SM_B0 32768
#define SM_B1 65536
#define SMEM_TOTAL 98304   // 96 KB
#define STAGE_PITCH 132    // floats

__global__ void __launch_bounds__(512, 1)
gemm_hmma_kernel() {
    extern __shared__ char smem[];
    const uint32_t smem_base = smem_u32(smem);
    const int t    = threadIdx.x;
    const int wid  = t >> 5;
    const int lane = t & 31;
    const int wrow = wid >> 3;     // 0..1  -> 64 b rows each
    const int wcol = wid & 7;      // 0..7  -> 32 p cols each
    const int b0   = blockIdx.x * 128;
    const int p0   = blockIdx.y * 256;

    const int abase[2] = {SM_A0, SM_A1};
    const int bbase[2] = {SM_B0, SM_B1};

    float acc[4][4][4];   // [mt][nt][4]
#pragma unroll
    for (int mt = 0; mt < 4; mt++)
#pragma unroll
        for (int nt = 0; nt < 4; nt++)
#pragma unroll
            for (int v = 0; v < 4; v++) acc[mt][nt][v] = 0.f;

    // chunk c: part = c>>2 (0:Xh.Wh, 1:Xl.Wh, 2:Xh.Wl), koff = (c&3)*64
    auto load_chunk = [&](int c, int buf) {
        int part = c >> 2;
        int koff = (c & 3) * 64;
        const __nv_bfloat16* As = (part == 1) ? g_Xl : g_Xh;
        const __nv_bfloat16* Ws = (part == 2) ? g_Wl : g_Wh;
#pragma unroll
        for (int i = 0; i < 2; i++) {
            int idx = t + i * 512;
            int row = idx >> 3, v = idx & 7;
            uint4 val = *(const uint4*)(As + (size_t)(b0 + row) * DN + koff + v * 8);
            *(uint4*)(smem + abase[buf] + SW128(row * 128 + v * 16)) = val;
        }
#pragma unroll
        for (int i = 0; i < 4; i++) {
            int idx = t + i * 512;
            int row = idx >> 3, v = idx & 7;
            uint4 val = *(const uint4*)(Ws + (size_t)(p0 + row) * DN + koff + v * 8);
            *(uint4*)(smem + bbase[buf] + SW128(row * 128 + v * 16)) = val;
        }
    };

    load_chunk(0, 0);
    __syncthreads();

    const int lm = lane & 15;
    const int lq = lane >> 4;

    for (int c = 0; c < 12; c++) {
        int cur = c & 1;
        if (c + 1 < 12) load_chunk(c + 1, cur ^ 1);

        uint32_t Ab = smem_base + abase[cur];
        uint32_t Bb = smem_base + bbase[cur];
#pragma unroll
        for (int ks = 0; ks < 4; ks++) {
            uint32_t a[4][4];
#pragma unroll
            for (int mt = 0; mt < 4; mt++)
                ldsm_x4(a[mt][0], a[mt][1], a[mt][2], a[mt][3],
                        Ab + SW128((wrow * 64 + mt * 16 + lm) * 128 + ks * 32 + lq * 16));
            uint32_t br[2][4];
#pragma unroll
            for (int bt = 0; bt < 2; bt++)
                ldsm_x4(br[bt][0], br[bt][1], br[bt][2], br[bt][3],
                        Bb + SW128((wcol * 32 + bt * 16 + lm) * 128 + ks * 32 + lq * 16));
#pragma unroll
            for (int mt = 0; mt < 4; mt++) {
#pragma unroll
                for (int bt = 0; bt < 2; bt++) {
                    uint32_t f0[2] = {br[bt][0], br[bt][2]};  // n8 tile: rows 0-7 of 16
                    uint32_t f1[2] = {br[bt][1], br[bt][3]};  // n8 tile: rows 8-15
                    mma16816(acc[mt][bt * 2 + 0], a[mt], f0);
                    mma16816(acc[mt][bt * 2 + 1], a[mt], f1);
                }
            }
        }
        __syncthreads();
    }

    // --- Epilogue ---
    // Acc layout: value v of tile (mt,nt): b = b0 + wrow*64 + mt*16 + lane/4 + (v>>1)*8
    //                                      p = p0 + wcol*32 + nt*8 + (lane%4)*2 + (v&1)
    float hx0[4], hx1[4];
#pragma unroll
    for (int mt = 0; mt < 4; mt++) {
        hx0[mt] = g_hx[b0 + wrow * 64 + mt * 16 + (lane >> 2)];
        hx1[mt] = g_hx[b0 + wrow * 64 + mt * 16 + (lane >> 2) + 8];
    }
    float g2l[4][2], Ap[4][2];
#pragma unroll
    for (int nt = 0; nt < 4; nt++) {
        int p = p0 + wcol * 32 + nt * 8 + (lane & 3) * 2;
        g2l[nt][0] = g_g2l[p];
        g2l[nt][1] = g_g2l[p + 1];
        Ap[nt][0]  = g_A[p];
        Ap[nt][1]  = g_A[p + 1];
    }

    float* stage = (float*)smem;

#pragma unroll
    for (int half = 0; half < 2; half++) {
        if ((wcol >> 2) == half) {
            int prow0 = (wcol & 3) * 32;  // stage-local p row base
#pragma unroll
            for (int mt = 0; mt < 4; mt++)
#pragma unroll
                for (int nt = 0; nt < 4; nt++)
#pragma unroll
                    for (int v = 0; v < 4; v++) {
                        float dot = acc[mt][nt][v];
                        float hxb = (v & 2) ? hx1[mt] : hx0[mt];
                        float tt = (dot - hxb) * g2l[nt][v & 1];
                        float tr = tt + 12582912.f;
                        float fn = tr - 12582912.f;
                        float f  = tt - fn;
                        float pl = 1.3333558146e-3f;
                        pl = fmaf(pl, f, 9.6181291076e-3f);
                        pl = fmaf(pl, f, 5.5504108664e-2f);
                        pl = fmaf(pl, f, 2.4022650696e-1f);
                        pl = fmaf(pl, f, 6.9314718056e-1f);
                        pl = fmaf(pl, f, 1.0f);
                        int ei = __float_as_int(tr) << 23;
                        float ex = __int_as_float(__float_as_int(pl) + ei) * Ap[nt][v & 1];
                        int pr = prow0 + nt * 8 + (lane & 3) * 2 + (v & 1);
                        int bc = wrow * 64 + mt * 16 + (lane >> 2) + ((v >> 1) * 8);
                        stage[pr * STAGE_PITCH + bc] = ex;
                    }
        }
        __syncthreads();
        // write half: 128 p rows x 128 b floats, coalesced
#pragma unroll
        for (int i = 0; i < 8; i++) {
            int idx = t + i * 512;
            int row = idx >> 5;          // 0..127
            int c4  = idx & 31;
            float4 val = *(const float4*)(stage + row * STAGE_PITCH + c4 * 4);
            *(float4*)(&g_s[(size_t)(p0 + half * 128 + row) * BN + b0 + c4 * 4]) = val;
        }
        __syncthreads();
    }
}

// ---------------------------------------------------------------------------
// Scan segments: affine composition per (b, segment)
// ---------------------------------------------------------------------------
__global__ void __launch_bounds__(256) scan_seg_kernel() {
    __shared__ float Us[SEGL][CN];
    const int seg = blockIdx.y;
    const int k0  = seg * SEGL;
    for (int i = threadIdx.x; i < SEGL * CN; i += 256)
        ((float*)Us)[i] = g_U[k0 * CN + i];
    __syncthreads();

    const int b = blockIdx.x * 256 + threadIdx.x;

    float A[CN], B[CN], D = 1.f;
#pragma unroll
    for (int c = 0; c < CN; c++) { A[c] = 1.f; B[c] = 0.f; }

    float cur[8], nxt[8];
#pragma unroll
    for (int i = 0; i < 8; i++) cur[i] = g_s[(size_t)(k0 + i) * BN + b];

    for (int kk = 0; kk < SEGL; kk += 8) {
        if (kk + 8 < SEGL) {
#pragma unroll
            for (int i = 0; i < 8; i++) nxt[i] = g_s[(size_t)(k0 + kk + 8 + i) * BN + b];
        }
#pragma unroll
        for (int i = 0; i < 8; i++) {
            float sk  = cur[i];
            float mn1 = 1.f - sk;
            float h   = mn1 * D;
            const float4* u4 = (const float4*)(&Us[kk + i][0]);
#pragma unroll
            for (int c4 = 0; c4 < 5; c4++) {
                float4 u = u4[c4];
                int c = c4 * 4;
                float a0 = fmaf(u.x, sk, mn1);
                float a1 = fmaf(u.y, sk, mn1);
                float a2 = fmaf(u.z, sk, mn1);
                float a3 = fmaf(u.w, sk, mn1);
                B[c + 0] = fmaf(a0, B[c + 0] + D, -h);
                B[c + 1] = fmaf(a1, B[c + 1] + D, -h);
                B[c + 2] = fmaf(a2, B[c + 2] + D, -h);
                B[c + 3] = fmaf(a3, B[c + 3] + D, -h);
                A[c + 0] *= a0;
                A[c + 1] *= a1;
                A[c + 2] *= a2;
                A[c + 3] *= a3;
            }
            D *= mn1;
        }
#pragma unroll
        for (int i = 0; i < 8; i++) cur[i] = nxt[i];
    }

#pragma unroll
    for (int c = 0; c < CN; c++) {
        g_segA[seg][c][b] = A[c];
        g_segB[seg][c][b] = B[c];
    }
    g_segD[seg][b] = D;
}

// ---------------------------------------------------------------------------
// Combine segments + normalize
// ---------------------------------------------------------------------------
__global__ void __launch_bounds__(256) combine_kernel(float* __restrict__ out) {
    const int gt = blockIdx.x * 256 + threadIdx.x;
    const int b  = gt >> 2;
    const int cg = gt & 3;

    float Bres[5], Dres;
    float Dseg[NSEG];
#pragma unroll
    for (int s = 0; s < NSEG; s++) Dseg[s] = g_segD[s][b];

#pragma unroll
    for (int j = 0; j < 5; j++) Bres[j] = g_segB[0][cg * 5 + j][b];
    Dres = Dseg[0];

#pragma unroll
    for (int s = 1; s < NSEG; s++) {
#pragma unroll
        for (int j = 0; j < 5; j++) {
            int c = cg * 5 + j;
            Bres[j] = Bres[j] * g_segA[s][c][b] + Dres * g_segB[s][c][b];
        }
        Dres *= Dseg[s];
    }

    float K = 0.f;
#pragma unroll
    for (int j = 0; j < 5; j++) K += Bres[j];
    K += __shfl_xor_sync(0xffffffffu, K, 1);
    K += __shfl_xor_sync(0xffffffffu, K, 2);
    K += Dres;
    float r = 1.f / K;

#pragma unroll
    for (int j = 0; j < 5; j++) out[b * (CN + 1) + cg * 5 + j] = Bres[j] * r;
    if (cg == 3) out[b * (CN + 1) + CN] = Dres * r;
}

// ---------------------------------------------------------------------------
extern "C" void kernel_launch(void* const* d_in, const int* in_sizes, int n_in,
                              void* d_out, int out_size) {
    const float* X     = (const float*)d_in[0];
    const float* W     = (const float*)d_in[1];
    const float* BETA  = (const float*)d_in[2];
    const float* alpha = (const float*)d_in[3];
    const float* gamma = (const float*)d_in[4];
    float* out = (float*)d_out;

    cudaFuncSetAttribute(gemm_hmma_kernel,
                         cudaFuncAttributeMaxDynamicSharedMemorySize, SMEM_TOTAL);

    prep_proto_kernel<<<PN, 32>>>(W, BETA, alpha, gamma);
    prep_x_kernel<<<BN / 8, 256>>>(X);

    dim3 ggrid(BN / 128, PN / 256);
    gemm_hmma_kernel<<<ggrid, 512, SMEM_TOTAL>>>();

    dim3 sgrid(BN / 256, NSEG);
    scan_seg_kernel<<<sgrid, 256>>>();

    combine_kernel<<<BN * 4 / 256, 256>>>(out);
}

// round 7
// speedup vs baseline: 2.6051x; 1.2437x over previous
#include <cuda_runtime.h>
#include <cuda_bf16.h>
#include <stdint.h>
#include <math.h>

#define BN 16384
#define DN 256
#define PN 512
#define CN 20
#define NSEG 8
#define SEGL (PN / NSEG)   // 64

// ---------------------------------------------------------------------------
// Device-global scratch (no allocations allowed)
// ---------------------------------------------------------------------------
__device__ float g_s[(size_t)PN * BN];   // s[k][b], 32 MB
__device__ float g_U[PN * CN];
__device__ float g_A[PN];                // alphap*exp(-g2*0.5*||W||^2)
__device__ float g_g2l[PN];              // g2 * log2(e)
__device__ float g_hx[BN];               // 0.5*||x_b||^2
__device__ float g_segA[NSEG][CN][BN];
__device__ float g_segB[NSEG][CN][BN];
__device__ float g_segD[NSEG][BN];

__device__ __nv_bfloat16 g_Xh[(size_t)BN * DN];
__device__ __nv_bfloat16 g_Xl[(size_t)BN * DN];
__device__ __nv_bfloat16 g_Wh[PN * DN];

#define SW128(off) ((off) ^ (((off) >> 3) & 0x70))

// ---------------------------------------------------------------------------
// mma.sync / ldmatrix / f32x2 wrappers (base sm_103 features)
// ---------------------------------------------------------------------------
__device__ __forceinline__ void ldsm_x4(uint32_t& r0, uint32_t& r1, uint32_t& r2,
                                        uint32_t& r3, uint32_t addr) {
    asm volatile("ldmatrix.sync.aligned.m8n8.x4.shared.b16 {%0,%1,%2,%3}, [%4];"
                 : "=r"(r0), "=r"(r1), "=r"(r2), "=r"(r3) : "r"(addr));
}
__device__ __forceinline__ void mma16816(float* d, const uint32_t* a, const uint32_t* b) {
    asm volatile("mma.sync.aligned.m16n8k16.row.col.f32.bf16.bf16.f32 "
                 "{%0,%1,%2,%3}, {%4,%5,%6,%7}, {%8,%9}, {%0,%1,%2,%3};"
                 : "+f"(d[0]), "+f"(d[1]), "+f"(d[2]), "+f"(d[3])
                 : "r"(a[0]), "r"(a[1]), "r"(a[2]), "r"(a[3]), "r"(b[0]), "r"(b[1]));
}
__device__ __forceinline__ uint32_t smem_u32(const void* p) {
    uint32_t a;
    asm("{ .reg .u64 t; cvta.to.shared.u64 t, %1; cvt.u32.u64 %0, t; }" : "=r"(a) : "l"(p));
    return a;
}
__device__ __forceinline__ uint64_t pack2(float x) {
    uint64_t r;
    asm("mov.b64 %0, {%1, %1};" : "=l"(r) : "f"(x));
    return r;
}
__device__ __forceinline__ uint64_t fma2(uint64_t a, uint64_t b, uint64_t c) {
    uint64_t d;
    asm("fma.rn.f32x2 %0, %1, %2, %3;" : "=l"(d) : "l"(a), "l"(b), "l"(c));
    return d;
}
__device__ __forceinline__ uint64_t add2(uint64_t a, uint64_t b) {
    uint64_t d;
    asm("add.rn.f32x2 %0, %1, %2;" : "=l"(d) : "l"(a), "l"(b));
    return d;
}
__device__ __forceinline__ uint64_t mul2(uint64_t a, uint64_t b) {
    uint64_t d;
    asm("mul.rn.f32x2 %0, %1, %2;" : "=l"(d) : "l"(a), "l"(b));
    return d;
}
__device__ __forceinline__ void unpack2(float& lo, float& hi, uint64_t v) {
    asm("mov.b64 {%0, %1}, %2;" : "=f"(lo), "=f"(hi) : "l"(v));
}

// ---------------------------------------------------------------------------
// Prep per-prototype: ||W||^2, U row, A, g2*log2e, W -> bf16 (hi only)
// ---------------------------------------------------------------------------
__global__ void prep_proto_kernel(const float* __restrict__ W,
                                  const float* __restrict__ BETA,
                                  const float* __restrict__ alpha,
                                  const float* __restrict__ gamma) {
    int k = blockIdx.x;
    int lane = threadIdx.x;

    float sum = 0.f;
    const float4* wr = (const float4*)(W + k * DN);
#pragma unroll
    for (int i = 0; i < 2; i++) {
        float4 v = wr[lane + i * 32];
        sum += v.x * v.x + v.y * v.y + v.z * v.z + v.w * v.w;
        int base = k * DN + (lane + i * 32) * 4;
        *(__nv_bfloat162*)(g_Wh + base) =
            __nv_bfloat162(__float2bfloat16(v.x), __float2bfloat16(v.y));
        *(__nv_bfloat162*)(g_Wh + base + 2) =
            __nv_bfloat162(__float2bfloat16(v.z), __float2bfloat16(v.w));
    }
#pragma unroll
    for (int o = 16; o; o >>= 1) sum += __shfl_xor_sync(0xffffffffu, sum, o);

    float b2 = 0.f;
    if (lane < CN) {
        float bb = BETA[k * CN + lane];
        b2 = bb * bb;
    }
    float bsum = b2;
#pragma unroll
    for (int o = 16; o; o >>= 1) bsum += __shfl_xor_sync(0xffffffffu, bsum, o);
    if (lane < CN) g_U[k * CN + lane] = b2 / bsum;

    if (lane == 0) {
        float g  = gamma[k];
        float g2 = g * g;
        float ap = 0.99f / (1.f + expf(-alpha[k]));
        g_g2l[k] = g2 * 1.4426950408889634f;
        g_A[k]   = ap * expf(-g2 * 0.5f * sum);
    }
}

// ---------------------------------------------------------------------------
// Prep per-batch: 0.5*||x||^2 and X -> bf16 hi/lo. One warp per row.
// ---------------------------------------------------------------------------
__global__ void prep_x_kernel(const float* __restrict__ X) {
    int row  = blockIdx.x * 8 + (threadIdx.x >> 5);
    int lane = threadIdx.x & 31;
    float sum = 0.f;
    const float4* xr = (const float4*)(X + (size_t)row * DN);
#pragma unroll
    for (int i = 0; i < 2; i++) {
        float4 v = xr[lane + i * 32];
        sum += v.x * v.x + v.y * v.y + v.z * v.z + v.w * v.w;
        size_t base = (size_t)row * DN + (lane + i * 32) * 4;
        __nv_bfloat16 h0 = __float2bfloat16(v.x);
        __nv_bfloat16 h1 = __float2bfloat16(v.y);
        __nv_bfloat16 h2 = __float2bfloat16(v.z);
        __nv_bfloat16 h3 = __float2bfloat16(v.w);
        __nv_bfloat16 l0 = __float2bfloat16(v.x - __bfloat162float(h0));
        __nv_bfloat16 l1 = __float2bfloat16(v.y - __bfloat162float(h1));
        __nv_bfloat16 l2 = __float2bfloat16(v.z - __bfloat162float(h2));
        __nv_bfloat16 l3 = __float2bfloat16(v.w - __bfloat162float(h3));
        *(__nv_bfloat162*)(g_Xh + base)     = __nv_bfloat162(h0, h1);
        *(__nv_bfloat162*)(g_Xh + base + 2) = __nv_bfloat162(h2, h3);
        *(__nv_bfloat162*)(g_Xl + base)     = __nv_bfloat162(l0, l1);
        *(__nv_bfloat162*)(g_Xl + base + 2) = __nv_bfloat162(l2, l3);
    }
#pragma unroll
    for (int o = 16; o; o >>= 1) sum += __shfl_xor_sync(0xffffffffu, sum, o);
    if (lane == 0) g_hx[row] = 0.5f * sum;
}

// ---------------------------------------------------------------------------
// HMMA GEMM: D[b,p] = (Xh+Xl).Wh  (K=512 effective; Wl term dropped, ~1e-4)
// Block 128b x 256p, 512 threads; warp tile 64x32. 8 virtual chunks
// (k-chunk x {Xh,Xl}); Wh chunk loaded ONCE per k (reused by both passes).
// ---------------------------------------------------------------------------
#define SM_A0 0
#define SM_A1 16384
#define SM_W0 32768
#define SM_W1 65536
#define SMEM_TOTAL 98304   // 96 KB
#define STAGE_PITCH 132    // floats

__global__ void __launch_bounds__(512, 1)
gemm_hmma_kernel() {
    extern __shared__ char smem[];
    const uint32_t smem_base = smem_u32(smem);
    const int t    = threadIdx.x;
    const int wid  = t >> 5;
    const int lane = t & 31;
    const int wrow = wid >> 3;     // 0..1  -> 64 b rows each
    const int wcol = wid & 7;      // 0..7  -> 32 p cols each
    const int b0   = blockIdx.x * 128;
    const int p0   = blockIdx.y * 256;

    const int abase[2] = {SM_A0, SM_A1};
    const int wbase[2] = {SM_W0, SM_W1};

    float acc[4][4][4];
#pragma unroll
    for (int mt = 0; mt < 4; mt++)
#pragma unroll
        for (int nt = 0; nt < 4; nt++)
#pragma unroll
            for (int v = 0; v < 4; v++) acc[mt][nt][v] = 0.f;

    auto load_a = [&](int part, int koff, int buf) {
        const __nv_bfloat16* As = part ? g_Xl : g_Xh;
#pragma unroll
        for (int i = 0; i < 2; i++) {
            int idx = t + i * 512;
            int row = idx >> 3, v = idx & 7;
            uint4 val = *(const uint4*)(As + (size_t)(b0 + row) * DN + koff + v * 8);
            *(uint4*)(smem + abase[buf] + SW128(row * 128 + v * 16)) = val;
        }
    };
    auto load_w = [&](int koff, int buf) {
#pragma unroll
        for (int i = 0; i < 4; i++) {
            int idx = t + i * 512;
            int row = idx >> 3, v = idx & 7;
            uint4 val = *(const uint4*)(g_Wh + (size_t)(p0 + row) * DN + koff + v * 8);
            *(uint4*)(smem + wbase[buf] + SW128(row * 128 + v * 16)) = val;
        }
    };

    load_a(0, 0, 0);
    load_w(0, 0);
    __syncthreads();

    const int lm = lane & 15;
    const int lq = lane >> 4;

    // virtual chunk c: k = c>>1, part = c&1 (0:Xh, 1:Xl). Wh[k] reused.
    for (int c = 0; c < 8; c++) {
        int ab = c & 1;
        int wb = (c >> 1) & 1;
        if (c < 7) {
            int nc = c + 1;
            load_a(nc & 1, (nc >> 1) * 64, ab ^ 1);
            if (!(nc & 1)) load_w((nc >> 1) * 64, (nc >> 1) & 1);
        }

        uint32_t Ab = smem_base + abase[ab];
        uint32_t Bb = smem_base + wbase[wb];
#pragma unroll
        for (int ks = 0; ks < 4; ks++) {
            uint32_t a[4][4];
#pragma unroll
            for (int mt = 0; mt < 4; mt++)
                ldsm_x4(a[mt][0], a[mt][1], a[mt][2], a[mt][3],
                        Ab + SW128((wrow * 64 + mt * 16 + lm) * 128 + ks * 32 + lq * 16));
            uint32_t br[2][4];
#pragma unroll
            for (int bt = 0; bt < 2; bt++)
                ldsm_x4(br[bt][0], br[bt][1], br[bt][2], br[bt][3],
                        Bb + SW128((wcol * 32 + bt * 16 + lm) * 128 + ks * 32 + lq * 16));
#pragma unroll
            for (int mt = 0; mt < 4; mt++) {
#pragma unroll
                for (int bt = 0; bt < 2; bt++) {
                    uint32_t f0[2] = {br[bt][0], br[bt][2]};
                    uint32_t f1[2] = {br[bt][1], br[bt][3]};
                    mma16816(acc[mt][bt * 2 + 0], a[mt], f0);
                    mma16816(acc[mt][bt * 2 + 1], a[mt], f1);
                }
            }
        }
        __syncthreads();
    }

    // --- Epilogue ---
    float hx0[4], hx1[4];
#pragma unroll
    for (int mt = 0; mt < 4; mt++) {
        hx0[mt] = g_hx[b0 + wrow * 64 + mt * 16 + (lane >> 2)];
        hx1[mt] = g_hx[b0 + wrow * 64 + mt * 16 + (lane >> 2) + 8];
    }
    float g2l[4][2], Ap[4][2];
#pragma unroll
    for (int nt = 0; nt < 4; nt++) {
        int p = p0 + wcol * 32 + nt * 8 + (lane & 3) * 2;
        g2l[nt][0] = g_g2l[p];
        g2l[nt][1] = g_g2l[p + 1];
        Ap[nt][0]  = g_A[p];
        Ap[nt][1]  = g_A[p + 1];
    }

    float* stage = (float*)smem;

#pragma unroll
    for (int half = 0; half < 2; half++) {
        if ((wcol >> 2) == half) {
            int prow0 = (wcol & 3) * 32;
#pragma unroll
            for (int mt = 0; mt < 4; mt++)
#pragma unroll
                for (int nt = 0; nt < 4; nt++)
#pragma unroll
                    for (int v = 0; v < 4; v++) {
                        float dot = acc[mt][nt][v];
                        float hxb = (v & 2) ? hx1[mt] : hx0[mt];
                        float tt = (dot - hxb) * g2l[nt][v & 1];
                        float tr = tt + 12582912.f;
                        float fn = tr - 12582912.f;
                        float f  = tt - fn;
                        float pl = 1.3333558146e-3f;
                        pl = fmaf(pl, f, 9.6181291076e-3f);
                        pl = fmaf(pl, f, 5.5504108664e-2f);
                        pl = fmaf(pl, f, 2.4022650696e-1f);
                        pl = fmaf(pl, f, 6.9314718056e-1f);
                        pl = fmaf(pl, f, 1.0f);
                        int ei = __float_as_int(tr) << 23;
                        float ex = __int_as_float(__float_as_int(pl) + ei) * Ap[nt][v & 1];
                        int pr = prow0 + nt * 8 + (lane & 3) * 2 + (v & 1);
                        int bc = wrow * 64 + mt * 16 + (lane >> 2) + ((v >> 1) * 8);
                        stage[pr * STAGE_PITCH + bc] = ex;
                    }
        }
        __syncthreads();
#pragma unroll
        for (int i = 0; i < 8; i++) {
            int idx = t + i * 512;
            int row = idx >> 5;
            int c4  = idx & 31;
            float4 val = *(const float4*)(stage + row * STAGE_PITCH + c4 * 4);
            *(float4*)(&g_s[(size_t)(p0 + half * 128 + row) * BN + b0 + c4 * 4]) = val;
        }
        __syncthreads();
    }
}

// ---------------------------------------------------------------------------
// Scan segments with packed f32x2: classes in 10 pairs.
//   a = U*s + (1-s);  B' = a*(B+D) - (1-s)*D;  A' = a*A;  D' = (1-s)*D
// ---------------------------------------------------------------------------
__global__ void __launch_bounds__(256) scan_seg_kernel() {
    __shared__ __align__(16) float Us[SEGL][CN];  // 80 B rows, 16B-aligned
    const int seg = blockIdx.y;
    const int k0  = seg * SEGL;
    for (int i = threadIdx.x; i < SEGL * CN; i += 256)
        ((float*)Us)[i] = g_U[k0 * CN + i];
    __syncthreads();

    const int b = blockIdx.x * 256 + threadIdx.x;

    uint64_t A2[10], B2[10];
    float D = 1.f;
    const uint64_t ONE2 = 0x3F8000003F800000ULL;
#pragma unroll
    for (int i = 0; i < 10; i++) { A2[i] = ONE2; B2[i] = 0ULL; }

    float cur[8], nxt[8];
#pragma unroll
    for (int i = 0; i < 8; i++) cur[i] = g_s[(size_t)(k0 + i) * BN + b];

    for (int kk = 0; kk < SEGL; kk += 8) {
        if (kk + 8 < SEGL) {
#pragma unroll
            for (int i = 0; i < 8; i++) nxt[i] = g_s[(size_t)(k0 + kk + 8 + i) * BN + b];
        }
#pragma unroll
        for (int i = 0; i < 8; i++) {
            float sk  = cur[i];
            float mn1 = 1.f - sk;
            float h   = mn1 * D;
            uint64_t ss2  = pack2(sk);
            uint64_t mn2  = pack2(mn1);
            uint64_t nh2  = pack2(-h);
            uint64_t DD2  = pack2(D);
            const ulonglong2* u2 = (const ulonglong2*)(&Us[kk + i][0]);
#pragma unroll
            for (int j = 0; j < 5; j++) {
                ulonglong2 up = u2[j];
                uint64_t a0 = fma2(up.x, ss2, mn2);
                uint64_t a1 = fma2(up.y, ss2, mn2);
                B2[j * 2 + 0] = fma2(a0, add2(B2[j * 2 + 0], DD2), nh2);
                B2[j * 2 + 1] = fma2(a1, add2(B2[j * 2 + 1], DD2), nh2);
                A2[j * 2 + 0] = mul2(A2[j * 2 + 0], a0);
                A2[j * 2 + 1] = mul2(A2[j * 2 + 1], a1);
            }
            D *= mn1;
        }
#pragma unroll
        for (int i = 0; i < 8; i++) cur[i] = nxt[i];
    }

#pragma unroll
    for (int i = 0; i < 10; i++) {
        float lo, hi;
        unpack2(lo, hi, A2[i]);
        g_segA[seg][i * 2 + 0][b] = lo;
        g_segA[seg][i * 2 + 1][b] = hi;
        unpack2(lo, hi, B2[i]);
        g_segB[seg][i * 2 + 0][b] = lo;
        g_segB[seg][i * 2 + 1][b] = hi;
    }
    g_segD[seg][b] = D;
}

// ---------------------------------------------------------------------------
// Combine segments + normalize
// ---------------------------------------------------------------------------
__global__ void __launch_bounds__(256) combine_kernel(float* __restrict__ out) {
    const int gt = blockIdx.x * 256 + threadIdx.x;
    const int b  = gt >> 2;
    const int cg = gt & 3;

    float Bres[5], Dres;
    float Dseg[NSEG];
#pragma unroll
    for (int s = 0; s < NSEG; s++) Dseg[s] = g_segD[s][b];

#pragma unroll
    for (int j = 0; j < 5; j++) Bres[j] = g_segB[0][cg * 5 + j][b];
    Dres = Dseg[0];

#pragma unroll
    for (int s = 1; s < NSEG; s++) {
#pragma unroll
        for (int j = 0; j < 5; j++) {
            int c = cg * 5 + j;
            Bres[j] = Bres[j] * g_segA[s][c][b] + Dres * g_segB[s][c][b];
        }
        Dres *= Dseg[s];
    }

    float K = 0.f;
#pragma unroll
    for (int j = 0; j < 5; j++) K += Bres[j];
    K += __shfl_xor_sync(0xffffffffu, K, 1);
    K += __shfl_xor_sync(0xffffffffu, K, 2);
    K += Dres;
    float r = 1.f / K;

#pragma unroll
    for (int j = 0; j < 5; j++) out[b * (CN + 1) + cg * 5 + j] = Bres[j] * r;
    if (cg == 3) out[b * (CN + 1) + CN] = Dres * r;
}

// ---------------------------------------------------------------------------
extern "C" void kernel_launch(void* const* d_in, const int* in_sizes, int n_in,
                              void* d_out, int out_size) {
    const float* X     = (const float*)d_in[0];
    const float* W     = (const float*)d_in[1];
    const float* BETA  = (const float*)d_in[2];
    const float* alpha = (const float*)d_in[3];
    const float* gamma = (const float*)d_in[4];
    float* out = (float*)d_out;

    cudaFuncSetAttribute(gemm_hmma_kernel,
                         cudaFuncAttributeMaxDynamicSharedMemorySize, SMEM_TOTAL);

    prep_proto_kernel<<<PN, 32>>>(W, BETA, alpha, gamma);
    prep_x_kernel<<<BN / 8, 256>>>(X);

    dim3 ggrid(BN / 128, PN / 256);
    gemm_hmma_kernel<<<ggrid, 512, SMEM_TOTAL>>>();

    dim3 sgrid(BN / 256, NSEG);
    scan_seg_kernel<<<sgrid, 256>>>();

    combine_kernel<<<BN * 4 / 256, 256>>>(out);
}